// round 7
// baseline (speedup 1.0000x reference)
#include <cuda_runtime.h>
#include <math.h>
#include <stdint.h>

#define N_NODES 100000
#define N_EDGES 600000
#define D 128
#define R 8
#define B_GRAPHS 64
#define L_LAYERS 3

#define NSEG (N_NODES * R)
#define EPAD_CAP 601088
#define NBLK_EDGE (EPAD_CAP / 128)  // 4696

#define SCAN_CHUNK 2048
#define SCAN_BPR ((N_NODES + SCAN_CHUNK - 1) / SCAN_CHUNK)  // 49
#define NBLK_SCAN (SCAN_BPR * R)                            // 392

#define NWMAT 16384                 // words per 128x128 matrix

// ---------------- scratch (device globals; zero-initialized at load) ----------
__device__ __align__(16) float g_x[N_NODES * D];            // 51.2 MB
__device__ __align__(16) float g_y[N_NODES * D];            // 51.2 MB
__device__ __align__(16) uint32_t g_wrelT[L_LAYERS * R * NWMAT]; // tf32 W^T [n][k]
__device__ __align__(16) uint32_t g_wrootT[L_LAYERS * NWMAT];
__device__ int   g_cnt[NSEG];
__device__ int   g_segoff[NSEG];
__device__ int   g_part[NBLK_SCAN];
__device__ int   g_pbase[NBLK_SCAN];
__device__ int   g_poff[R + 1];
__device__ int   g_esrc[EPAD_CAP];
__device__ int   g_edst[EPAD_CAP];
__device__ float g_escale[EPAD_CAP];
__device__ float g_pool[B_GRAPHS * D];
__device__ float g_pcnt[B_GRAPHS];

// ---------------- counting + scan ---------------------------------------------
__global__ void k_count(const int* __restrict__ ei, const int* __restrict__ et) {
    int e = blockIdx.x * blockDim.x + threadIdx.x;
    if (e >= N_EDGES) return;
    atomicAdd(&g_cnt[et[e] * N_NODES + ei[N_EDGES + e]], 1);
}

__global__ void k_scanA() {
    __shared__ int ssum[256];
    int b = blockIdx.x;
    int rel = b / SCAN_BPR, cb = b % SCAN_BPR;
    int base = rel * N_NODES + cb * SCAN_CHUNK;
    int lim = rel * N_NODES + N_NODES;
    int t = threadIdx.x;
    int s = 0;
#pragma unroll
    for (int i = 0; i < 8; i++) {
        int idx = base + t * 8 + i;
        if (idx < lim) s += g_cnt[idx];
    }
    ssum[t] = s;
    __syncthreads();
    for (int o = 128; o > 0; o >>= 1) {
        if (t < o) ssum[t] += ssum[t + o];
        __syncthreads();
    }
    if (t == 0) g_part[b] = ssum[0];
}

__global__ void k_scanB() {
    if (threadIdx.x == 0) {
        int off = 0;
        for (int r = 0; r < R; r++) {
            g_poff[r] = off;
            int tot = 0;
            for (int cb = 0; cb < SCAN_BPR; cb++) {
                g_pbase[r * SCAN_BPR + cb] = off + tot;
                tot += g_part[r * SCAN_BPR + cb];
            }
            off += ((tot + 127) >> 7) << 7;
        }
        g_poff[R] = off;
    }
}

__global__ void k_scanC() {
    __shared__ int sv[256];
    int b = blockIdx.x;
    int rel = b / SCAN_BPR, cb = b % SCAN_BPR;
    int base = rel * N_NODES + cb * SCAN_CHUNK;
    int lim = rel * N_NODES + N_NODES;
    int t = threadIdx.x;
    int loc[8];
    int s = 0;
#pragma unroll
    for (int i = 0; i < 8; i++) {
        int idx = base + t * 8 + i;
        loc[i] = s;
        if (idx < lim) s += g_cnt[idx];
    }
    sv[t] = s;
    __syncthreads();
    for (int o = 1; o < 256; o <<= 1) {
        int add = (t >= o) ? sv[t - o] : 0;
        __syncthreads();
        sv[t] += add;
        __syncthreads();
    }
    int texcl = sv[t] - s;
    int bb = g_pbase[b];
#pragma unroll
    for (int i = 0; i < 8; i++) {
        int idx = base + t * 8 + i;
        if (idx < lim) g_segoff[idx] = bb + texcl + loc[i];
    }
}

__global__ void k_sort(const int* __restrict__ ei, const int* __restrict__ et) {
    int e = blockIdx.x * blockDim.x + threadIdx.x;
    if (e >= N_EDGES) return;
    int t = et[e];
    int src = ei[e];
    int dst = ei[N_EDGES + e];
    int seg = t * N_NODES + dst;
    int cnt = g_cnt[seg];
    int pos = atomicAdd(&g_segoff[seg], 1);
    g_esrc[pos] = src;
    g_edst[pos] = dst;
    g_escale[pos] = 1.0f / (float)max(cnt, 1);
}

// ---------------- tf32 helpers --------------------------------------------------
__device__ __forceinline__ uint32_t f2tf32(float x) {
    uint32_t r;
    asm("cvt.rna.tf32.f32 %0, %1;" : "=r"(r) : "f"(x));
    return r;
}

__device__ __forceinline__ uint4 cvt4(float4 v, int dorelu) {
    if (dorelu) {
        v.x = fmaxf(v.x, 0.f); v.y = fmaxf(v.y, 0.f);
        v.z = fmaxf(v.z, 0.f); v.w = fmaxf(v.w, 0.f);
    }
    uint4 t4;
    t4.x = f2tf32(v.x); t4.y = f2tf32(v.y);
    t4.z = f2tf32(v.z); t4.w = f2tf32(v.w);
    return t4;
}

__device__ __forceinline__ void ldsm_x4(uint32_t* r, uint32_t addr) {
    asm volatile("ldmatrix.sync.aligned.m8n8.x4.shared.b16 {%0,%1,%2,%3}, [%4];"
                 : "=r"(r[0]), "=r"(r[1]), "=r"(r[2]), "=r"(r[3]) : "r"(addr));
}
__device__ __forceinline__ void ldsm_x2(uint32_t* r, uint32_t addr) {
    asm volatile("ldmatrix.sync.aligned.m8n8.x2.shared.b16 {%0,%1}, [%2];"
                 : "=r"(r[0]), "=r"(r[1]) : "r"(addr));
}

#define MMA_TF32(ac, a0, a1, a2, a3, b0, b1)                                   \
    asm volatile(                                                              \
        "mma.sync.aligned.m16n8k8.row.col.f32.tf32.tf32.f32 "                  \
        "{%0,%1,%2,%3}, {%4,%5,%6,%7}, {%8,%9}, {%0,%1,%2,%3};"                \
        : "+f"((ac)[0]), "+f"((ac)[1]), "+f"((ac)[2]), "+f"((ac)[3])           \
        : "r"(a0), "r"(a1), "r"(a2), "r"(a3), "r"(b0), "r"(b1))

// ---------------- weight pre-pack: fp32 [k][n] -> tf32 W^T [n][k] --------------
__global__ void k_cvtW(const float* __restrict__ rel_w,
                       const float* __restrict__ root_w) {
    int idx = blockIdx.x * blockDim.x + threadIdx.x;
    int total = (L_LAYERS * R + L_LAYERS) * NWMAT;
    if (idx >= total) return;
    int mat = idx >> 14, wi = idx & (NWMAT - 1);
    int n = wi >> 7, k = wi & 127;
    if (mat < L_LAYERS * R) {
        g_wrelT[idx] = f2tf32(rel_w[(size_t)mat * NWMAT + k * 128 + n]);
    } else {
        int m2 = mat - L_LAYERS * R;
        g_wrootT[m2 * NWMAT + wi] =
            f2tf32(root_w[(size_t)m2 * NWMAT + k * 128 + n]);
    }
}

// x = node_emb[node_type]
__global__ void k_gather(const int* __restrict__ node_type,
                         const float* __restrict__ node_emb) {
    int idx = blockIdx.x * blockDim.x + threadIdx.x;
    if (idx >= N_NODES * (D / 4)) return;
    int n = idx >> 5;
    int f = idx & 31;
    ((float4*)g_x)[idx] =
        ((const float4*)(node_emb + (size_t)node_type[n] * D))[f];
}

// ---------------- root: y = x_eff @ Wroot + bias --------------------------------
#define SA_STR 20
#define SB_STR 20

__global__ void __launch_bounds__(256, 2)
k_root(int l, int flip, int dorelu, const float* __restrict__ bias) {
    const float* xin = flip ? g_y : g_x;
    float* yout = flip ? g_x : g_y;
    const uint32_t* Wt = g_wrootT + (size_t)l * NWMAT;

    __shared__ uint32_t sA[128 * SA_STR];
    __shared__ uint32_t sB[128 * SB_STR];
    __shared__ float sBias[128];

    int tid = threadIdx.x;
    int lane = tid & 31;
    int w = tid >> 5;
    int g = lane >> 2, tg = lane & 3;
    int rm = (w & 1) * 64, cn = (w >> 1) * 32;
    int row0 = blockIdx.x * 128;

    if (tid < 128) sBias[tid] = bias[tid];

    // A prefetch setup (2 rows per thread, one float4 per row per chunk)
    int mA0 = tid >> 2, k4 = tid & 3;
    int mA1 = mA0 + 64;
    int rowA0c = min(row0 + mA0, N_NODES - 1);
    int rowA1c = min(row0 + mA1, N_NODES - 1);
    bool vA0 = (row0 + mA0) < N_NODES;
    bool vA1 = (row0 + mA1) < N_NODES;
    const float* a0p = xin + (size_t)rowA0c * D + k4 * 4;
    const float* a1p = xin + (size_t)rowA1c * D + k4 * 4;

    // B prefetch setup (2 uint4 per thread per chunk; tile = 512 uint4)
    int nB0 = tid >> 2, qB = tid & 3;
    int nB1 = nB0 + 64;
    const uint4* w0p = (const uint4*)Wt + nB0 * 32 + qB;
    const uint4* w1p = (const uint4*)Wt + nB1 * 32 + qB;

    // ldmatrix per-lane base addresses
    uint32_t saA = (uint32_t)__cvta_generic_to_shared(sA);
    uint32_t saB = (uint32_t)__cvta_generic_to_shared(sB);
    uint32_t aBase = saA + 4u * ((rm + (lane & 15)) * SA_STR + ((lane >> 4) << 2));
    uint32_t bBase = saB + 4u * ((cn + (lane & 7)) * SB_STR + (((lane >> 3) & 1) << 2));

    float acc[4][4][4];
#pragma unroll
    for (int mi = 0; mi < 4; mi++)
#pragma unroll
        for (int ni = 0; ni < 4; ni++)
#pragma unroll
            for (int c = 0; c < 4; c++) acc[mi][ni][c] = 0.f;

    float4 pa0 = *(const float4*)a0p;
    float4 pa1 = *(const float4*)a1p;
    uint4 pb0 = w0p[0];
    uint4 pb1 = w1p[0];

    for (int kb = 0; kb < 8; kb++) {
        float4 qa0 = vA0 ? pa0 : make_float4(0.f, 0.f, 0.f, 0.f);
        float4 qa1 = vA1 ? pa1 : make_float4(0.f, 0.f, 0.f, 0.f);
        ((uint4*)(sA + mA0 * SA_STR))[k4] = cvt4(qa0, dorelu);
        ((uint4*)(sA + mA1 * SA_STR))[k4] = cvt4(qa1, dorelu);
        ((uint4*)(sB + nB0 * SB_STR))[qB] = pb0;
        ((uint4*)(sB + nB1 * SB_STR))[qB] = pb1;
        __syncthreads();
        if (kb < 7) {
            pa0 = *(const float4*)(a0p + (kb + 1) * 16);
            pa1 = *(const float4*)(a1p + (kb + 1) * 16);
            pb0 = w0p[(kb + 1) * 4];
            pb1 = w1p[(kb + 1) * 4];
        }
#pragma unroll
        for (int kk = 0; kk < 16; kk += 8) {
            uint32_t af[4][4], bf[4][2];
#pragma unroll
            for (int mi = 0; mi < 4; mi++)
                ldsm_x4(af[mi], aBase + 4u * (mi * 16 * SA_STR + kk));
#pragma unroll
            for (int ni = 0; ni < 4; ni++)
                ldsm_x2(bf[ni], bBase + 4u * (ni * 8 * SB_STR + kk));
#pragma unroll
            for (int mi = 0; mi < 4; mi++)
#pragma unroll
                for (int ni = 0; ni < 4; ni++)
                    MMA_TF32(acc[mi][ni], af[mi][0], af[mi][1], af[mi][2],
                             af[mi][3], bf[ni][0], bf[ni][1]);
        }
        __syncthreads();
    }

#pragma unroll
    for (int mi = 0; mi < 4; mi++)
#pragma unroll
        for (int ni = 0; ni < 4; ni++) {
            int col = cn + ni * 8 + 2 * tg;
            int row1 = row0 + rm + mi * 16 + g;
            int row2 = row1 + 8;
            float b0 = sBias[col], b1 = sBias[col + 1];
            if (row1 < N_NODES) {
                float2 o = {acc[mi][ni][0] + b0, acc[mi][ni][1] + b1};
                *(float2*)(yout + (size_t)row1 * D + col) = o;
            }
            if (row2 < N_NODES) {
                float2 o = {acc[mi][ni][2] + b0, acc[mi][ni][3] + b1};
                *(float2*)(yout + (size_t)row2 * D + col) = o;
            }
        }
}

// ---------------- edge GEMM-scatter: y[dst] += scale * (x_eff[src] @ W_rel) ----
__global__ void __launch_bounds__(256, 2)
k_edge(int l, int flip, int dorelu) {
    const float* xin = flip ? g_y : g_x;
    float* yout = flip ? g_x : g_y;

    __shared__ union {
        struct { uint32_t a[128 * SA_STR]; uint32_t b[128 * SB_STR]; } mm;
        float stage[128 * 132];
    } u;
    __shared__ int sSrc[128];
    __shared__ int sDst[128];
    __shared__ float sScale[128];
    __shared__ int sRel;

    int tid = threadIdx.x;
    int lane = tid & 31;
    int w = tid >> 5;
    int g = lane >> 2, tg = lane & 3;
    int rm = (w & 1) * 64, cn = (w >> 1) * 32;
    int row0 = blockIdx.x * 128;

    if (tid < 128) {
        sSrc[tid] = g_esrc[row0 + tid];
        sDst[tid] = g_edst[row0 + tid];
        sScale[tid] = g_escale[row0 + tid];
    }
    if (tid == 0) {
        int r = 0;
#pragma unroll
        for (int i = 1; i < R; i++)
            if (row0 >= g_poff[i]) r = i;
        sRel = r;
    }
    __syncthreads();
    const uint32_t* Wt = g_wrelT + ((size_t)l * R + sRel) * NWMAT;

    int mA0 = tid >> 2, k4 = tid & 3;
    int mA1 = mA0 + 64;
    const float* a0p = xin + (size_t)sSrc[mA0] * D + k4 * 4;
    const float* a1p = xin + (size_t)sSrc[mA1] * D + k4 * 4;

    int nB0 = tid >> 2, qB = tid & 3;
    int nB1 = nB0 + 64;
    const uint4* w0p = (const uint4*)Wt + nB0 * 32 + qB;
    const uint4* w1p = (const uint4*)Wt + nB1 * 32 + qB;

    uint32_t saA = (uint32_t)__cvta_generic_to_shared(u.mm.a);
    uint32_t saB = (uint32_t)__cvta_generic_to_shared(u.mm.b);
    uint32_t aBase = saA + 4u * ((rm + (lane & 15)) * SA_STR + ((lane >> 4) << 2));
    uint32_t bBase = saB + 4u * ((cn + (lane & 7)) * SB_STR + (((lane >> 3) & 1) << 2));

    float acc[4][4][4];
#pragma unroll
    for (int mi = 0; mi < 4; mi++)
#pragma unroll
        for (int ni = 0; ni < 4; ni++)
#pragma unroll
            for (int c = 0; c < 4; c++) acc[mi][ni][c] = 0.f;

    float4 pa0 = *(const float4*)a0p;
    float4 pa1 = *(const float4*)a1p;
    uint4 pb0 = w0p[0];
    uint4 pb1 = w1p[0];

    for (int kb = 0; kb < 8; kb++) {
        ((uint4*)(u.mm.a + mA0 * SA_STR))[k4] = cvt4(pa0, dorelu);
        ((uint4*)(u.mm.a + mA1 * SA_STR))[k4] = cvt4(pa1, dorelu);
        ((uint4*)(u.mm.b + nB0 * SB_STR))[qB] = pb0;
        ((uint4*)(u.mm.b + nB1 * SB_STR))[qB] = pb1;
        __syncthreads();
        if (kb < 7) {
            pa0 = *(const float4*)(a0p + (kb + 1) * 16);
            pa1 = *(const float4*)(a1p + (kb + 1) * 16);
            pb0 = w0p[(kb + 1) * 4];
            pb1 = w1p[(kb + 1) * 4];
        }
#pragma unroll
        for (int kk = 0; kk < 16; kk += 8) {
            uint32_t af[4][4], bf[4][2];
#pragma unroll
            for (int mi = 0; mi < 4; mi++)
                ldsm_x4(af[mi], aBase + 4u * (mi * 16 * SA_STR + kk));
#pragma unroll
            for (int ni = 0; ni < 4; ni++)
                ldsm_x2(bf[ni], bBase + 4u * (ni * 8 * SB_STR + kk));
#pragma unroll
            for (int mi = 0; mi < 4; mi++)
#pragma unroll
                for (int ni = 0; ni < 4; ni++)
                    MMA_TF32(acc[mi][ni], af[mi][0], af[mi][1], af[mi][2],
                             af[mi][3], bf[ni][0], bf[ni][1]);
        }
        __syncthreads();
    }

    // stage all 128 rows, scale folded (padding rows have scale 0 -> zeros)
#pragma unroll
    for (int mi = 0; mi < 4; mi++)
#pragma unroll
        for (int ni = 0; ni < 4; ni++) {
            int col = cn + ni * 8 + 2 * tg;
            int row1 = rm + mi * 16 + g;
            int row2 = row1 + 8;
            float s1 = sScale[row1], s2 = sScale[row2];
            u.stage[row1 * 132 + col] = acc[mi][ni][0] * s1;
            u.stage[row1 * 132 + col + 1] = acc[mi][ni][1] * s1;
            u.stage[row2 * 132 + col] = acc[mi][ni][2] * s2;
            u.stage[row2 * 132 + col + 1] = acc[mi][ni][3] * s2;
        }
    __syncthreads();

    // merged scatter: 32 f4-columns x 8 walkers of 16 sorted rows each
    {
        int col4 = tid & 31;
        int wk = tid >> 5;
        int r0 = wk * 16;
        float4 a4 = *(float4*)&u.stage[r0 * 132 + col4 * 4];
        int cur = sDst[r0];
        bool any = (sScale[r0] != 0.f);
#pragma unroll
        for (int rr = r0 + 1; rr < r0 + 16; rr++) {
            int dd = sDst[rr];
            float4 v = *(float4*)&u.stage[rr * 132 + col4 * 4];
            bool act = (sScale[rr] != 0.f);
            if (dd != cur) {
                if (any)
                    atomicAdd((float4*)(yout + (size_t)cur * D) + col4, a4);
                a4 = v;
                cur = dd;
                any = act;
            } else {
                a4.x += v.x; a4.y += v.y; a4.z += v.z; a4.w += v.w;
                any = any || act;
            }
        }
        if (any)
            atomicAdd((float4*)(yout + (size_t)cur * D) + col4, a4);
    }
}

// ---------------- global mean pool (relu applied on read) ----------------------
__global__ void k_pool(const int* __restrict__ batch) {
    const float* x = g_y;               // layer-2 output (pre-relu)
    int d = threadIdx.x;                // 128 threads == D
    int start = blockIdx.x * 256;
    if (start >= N_NODES) return;
    int end = min(start + 256, N_NODES);
    float acc = 0.f, c = 0.f;
    int curb = batch[start];
    for (int n = start; n < end; n++) {
        int bb = batch[n];
        if (bb != curb) {
            atomicAdd(&g_pool[curb * D + d], acc);
            if (d == 0) atomicAdd(&g_pcnt[curb], c);
            acc = 0.f; c = 0.f; curb = bb;
        }
        acc += fmaxf(x[(size_t)n * D + d], 0.f);
        c += 1.f;
    }
    atomicAdd(&g_pool[curb * D + d], acc);
    if (d == 0) atomicAdd(&g_pcnt[curb], c);
}

// ---------------- MLP heads ----------------------------------------------------
__global__ void k_head(const float* __restrict__ rw1, const float* __restrict__ rb1,
                       const float* __restrict__ rw2, const float* __restrict__ rb2,
                       const float* __restrict__ sw1, const float* __restrict__ sb1,
                       const float* __restrict__ sw2, const float* __restrict__ sb2,
                       float* __restrict__ out) {
    int b = blockIdx.x;
    int j = threadIdx.x;
    __shared__ float gv[128];
    __shared__ float red[4];
    float inv = 1.f / fmaxf(g_pcnt[b], 1.f);
    gv[j] = g_pool[b * D + j] * inv;
    __syncthreads();

#pragma unroll
    for (int head = 0; head < 2; head++) {
        const float* W1 = head ? sw1 : rw1;
        const float* B1 = head ? sb1 : rb1;
        const float* W2 = head ? sw2 : rw2;
        const float* B2 = head ? sb2 : rb2;
        float h = B1[j];
#pragma unroll 8
        for (int d = 0; d < D; d++) h += gv[d] * W1[d * D + j];
        h = fmaxf(h, 0.f);
        float p = h * W2[j];
#pragma unroll
        for (int o = 16; o > 0; o >>= 1) p += __shfl_down_sync(0xffffffffu, p, o);
        if ((j & 31) == 0) red[j >> 5] = p;
        __syncthreads();
        if (j == 0) out[head * B_GRAPHS + b] = red[0] + red[1] + red[2] + red[3] + B2[0];
        __syncthreads();
    }
}

// ---------------- tail: restore zero state for next graph replay ---------------
__global__ void k_tail() {
    int i = blockIdx.x * blockDim.x + threadIdx.x;
    if (i < NSEG) g_cnt[i] = 0;
    if (i < B_GRAPHS * D) g_pool[i] = 0.f;
    if (i < B_GRAPHS) g_pcnt[i] = 0.f;
}

// ---------------- launch --------------------------------------------------------
extern "C" void kernel_launch(void* const* d_in, const int* in_sizes, int n_in,
                              void* d_out, int out_size) {
    const int* node_type = (const int*)d_in[0];
    const int* edge_index = (const int*)d_in[1];
    const int* edge_type = (const int*)d_in[2];
    const int* batch = (const int*)d_in[3];
    const float* node_emb = (const float*)d_in[4];
    const float* rel_w = (const float*)d_in[5];
    const float* root_w = (const float*)d_in[6];
    const float* bias = (const float*)d_in[7];
    const float* risk_w1 = (const float*)d_in[8];
    const float* risk_b1 = (const float*)d_in[9];
    const float* risk_w2 = (const float*)d_in[10];
    const float* risk_b2 = (const float*)d_in[11];
    const float* safe_w1 = (const float*)d_in[12];
    const float* safe_b1 = (const float*)d_in[13];
    const float* safe_w2 = (const float*)d_in[14];
    const float* safe_b2 = (const float*)d_in[15];
    float* out = (float*)d_out;

    k_count<<<(N_EDGES + 255) / 256, 256>>>(edge_index, edge_type);
    k_scanA<<<NBLK_SCAN, 256>>>();
    k_scanB<<<1, 32>>>();
    k_scanC<<<NBLK_SCAN, 256>>>();
    k_sort<<<(N_EDGES + 255) / 256, 256>>>(edge_index, edge_type);
    k_cvtW<<<((L_LAYERS * R + L_LAYERS) * NWMAT + 255) / 256, 256>>>(rel_w, root_w);
    k_gather<<<(N_NODES * (D / 4) + 255) / 256, 256>>>(node_type, node_emb);

    for (int l = 0; l < L_LAYERS; l++) {
        int flip = l & 1;       // 0: in g_x -> out g_y ; 1: in g_y -> out g_x
        int dorelu = (l > 0);
        k_root<<<(N_NODES + 127) / 128, 256>>>(l, flip, dorelu,
                                               bias + (size_t)l * D);
        k_edge<<<NBLK_EDGE, 256>>>(l, flip, dorelu);
    }

    k_pool<<<(N_NODES + 255) / 256, 128>>>(batch);
    k_head<<<B_GRAPHS, 128>>>(risk_w1, risk_b1, risk_w2, risk_b2,
                              safe_w1, safe_b1, safe_w2, safe_b2, out);
    k_tail<<<(NSEG + 255) / 256, 256>>>();
}